// round 1
// baseline (speedup 1.0000x reference)
#include <cuda_runtime.h>

#define N_NODES 10000
#define N_EDGES 160000
#define DIM     1280
#define D4      (DIM / 4)   // 320 float4 per row

// Scratch (device globals — no allocation allowed)
__device__ float g_outw[N_NODES];
__device__ float g_q[N_NODES];
__device__ float g_coef[N_NODES];
__device__ float g_C;
__device__ float g_S1[DIM];       // sum_s coef[s] * h0[s]
__device__ float g_msum[DIM];     // sum_s h0[s]
__device__ float g_v1[DIM];       // layer-1 weighted-mean output

// ---------------- K0: zero scratch ----------------
__global__ void k_zero() {
    int i = blockIdx.x * blockDim.x + threadIdx.x;
    const int total = 2 * N_NODES + 2 * DIM + 1;
    for (; i < total; i += gridDim.x * blockDim.x) {
        if (i < N_NODES)                      g_outw[i] = 0.f;
        else if (i < 2 * N_NODES)             g_q[i - N_NODES] = 0.f;
        else if (i < 2 * N_NODES + DIM)       g_S1[i - 2 * N_NODES] = 0.f;
        else if (i < 2 * N_NODES + 2 * DIM)   g_msum[i - 2 * N_NODES - DIM] = 0.f;
        else                                  g_C = 0.f;
    }
}

__device__ __forceinline__ float edge_w(float x) {
    return 1.0f / (x * x + 1e-6f);
}

// ---------------- K1: outw[src] += ew ----------------
__global__ void k_outw(const float* __restrict__ ef, const int* __restrict__ src) {
    int e = blockIdx.x * blockDim.x + threadIdx.x;
    if (e < N_EDGES) {
        atomicAdd(&g_outw[src[e]], edge_w(ef[e]));
    }
}

// ---------------- K2: q[src] += ew * (1 + outw[dst]) ----------------
__global__ void k_q(const float* __restrict__ ef, const int* __restrict__ src,
                    const int* __restrict__ dst) {
    int e = blockIdx.x * blockDim.x + threadIdx.x;
    if (e < N_EDGES) {
        float w = edge_w(ef[e]);
        atomicAdd(&g_q[src[e]], w * (1.0f + g_outw[dst[e]]));
    }
}

// ---------------- K3: coef[s] = 1 + outw + q ; C = sum(1 + outw) ----------------
__global__ void k_coef() {
    int s = blockIdx.x * blockDim.x + threadIdx.x;
    float c = 0.f;
    if (s < N_NODES) {
        c = 1.0f + g_outw[s];
        g_coef[s] = c + g_q[s];
    }
    #pragma unroll
    for (int o = 16; o; o >>= 1) c += __shfl_down_sync(0xffffffffu, c, o);
    __shared__ float sh[8];
    if ((threadIdx.x & 31) == 0) sh[threadIdx.x >> 5] = c;
    __syncthreads();
    if (threadIdx.x < 8) {
        float v = sh[threadIdx.x];
        #pragma unroll
        for (int o = 4; o; o >>= 1) v += __shfl_down_sync(0xffu, v, o);
        if (threadIdx.x == 0) atomicAdd(&g_C, v);
    }
}

// ---------------- K4: dominant pass — weighted + plain column sums ----------------
// block = 320 threads, each thread owns one float4 slice of the 1280 columns.
// grid = row chunks; partials combined with atomics (2560 addresses, low contention).
__global__ void __launch_bounds__(D4) k_colsum(const float* __restrict__ h0) {
    const int t = threadIdx.x;   // 0..319
    const float4* __restrict__ h4 = (const float4*)h0;
    float4 aw = make_float4(0.f, 0.f, 0.f, 0.f);
    float4 as = make_float4(0.f, 0.f, 0.f, 0.f);
    for (int s = blockIdx.x; s < N_NODES; s += gridDim.x) {
        float c = __ldg(&g_coef[s]);
        float4 v = __ldg(&h4[(long)s * D4 + t]);
        aw.x = fmaf(c, v.x, aw.x); aw.y = fmaf(c, v.y, aw.y);
        aw.z = fmaf(c, v.z, aw.z); aw.w = fmaf(c, v.w, aw.w);
        as.x += v.x; as.y += v.y; as.z += v.z; as.w += v.w;
    }
    int d = 4 * t;
    atomicAdd(&g_S1[d + 0], aw.x); atomicAdd(&g_S1[d + 1], aw.y);
    atomicAdd(&g_S1[d + 2], aw.z); atomicAdd(&g_S1[d + 3], aw.w);
    atomicAdd(&g_msum[d + 0], as.x); atomicAdd(&g_msum[d + 1], as.y);
    atomicAdd(&g_msum[d + 2], as.z); atomicAdd(&g_msum[d + 3], as.w);
}

// ---------------- K5: v1 = (S1/N) @ W1^T + (C/N) * b1 ----------------
// one warp per output row; row of W is contiguous -> coalesced float4 dot.
__global__ void k_mv1(const float* __restrict__ W1, const float* __restrict__ b1) {
    int warp = (blockIdx.x * blockDim.x + threadIdx.x) >> 5;
    int lane = threadIdx.x & 31;
    if (warp >= DIM) return;
    const float4* __restrict__ row = (const float4*)(W1 + (long)warp * DIM);
    const float4* __restrict__ s1  = (const float4*)g_S1;
    float acc = 0.f;
    #pragma unroll
    for (int j = lane; j < D4; j += 32) {
        float4 w = __ldg(&row[j]);
        float4 s = s1[j];
        acc += w.x * s.x + w.y * s.y + w.z * s.z + w.w * s.w;
    }
    #pragma unroll
    for (int o = 16; o; o >>= 1) acc += __shfl_down_sync(0xffffffffu, acc, o);
    if (lane == 0) {
        const float invN = 1.0f / (float)N_NODES;
        g_v1[warp] = acc * invN + g_C * invN * __ldg(&b1[warp]);
    }
}

// ---------------- K6: out = v1 @ W2^T + b2 + msum/N ----------------
__global__ void k_mv2(const float* __restrict__ W2, const float* __restrict__ b2,
                      float* __restrict__ out) {
    int warp = (blockIdx.x * blockDim.x + threadIdx.x) >> 5;
    int lane = threadIdx.x & 31;
    if (warp >= DIM) return;
    const float4* __restrict__ row = (const float4*)(W2 + (long)warp * DIM);
    const float4* __restrict__ v1  = (const float4*)g_v1;
    float acc = 0.f;
    #pragma unroll
    for (int j = lane; j < D4; j += 32) {
        float4 w = __ldg(&row[j]);
        float4 v = v1[j];
        acc += w.x * v.x + w.y * v.y + w.z * v.z + w.w * v.w;
    }
    #pragma unroll
    for (int o = 16; o; o >>= 1) acc += __shfl_down_sync(0xffffffffu, acc, o);
    if (lane == 0) {
        const float invN = 1.0f / (float)N_NODES;
        out[warp] = acc + __ldg(&b2[warp]) + g_msum[warp] * invN;
    }
}

extern "C" void kernel_launch(void* const* d_in, const int* in_sizes, int n_in,
                              void* d_out, int out_size) {
    const float* node = (const float*)d_in[0];   // [N, D]
    const float* ef   = (const float*)d_in[1];   // [E]
    const int*   ei   = (const int*)  d_in[2];   // [2, E]
    const float* W1   = (const float*)d_in[3];
    const float* b1   = (const float*)d_in[4];
    const float* W2   = (const float*)d_in[5];
    const float* b2   = (const float*)d_in[6];
    float* out = (float*)d_out;

    const int* src = ei;
    const int* dst = ei + N_EDGES;

    k_zero<<<96, 256>>>();
    k_outw<<<(N_EDGES + 255) / 256, 256>>>(ef, src);
    k_q<<<(N_EDGES + 255) / 256, 256>>>(ef, src, dst);
    k_coef<<<(N_NODES + 255) / 256, 256>>>();
    k_colsum<<<148, D4>>>(node);
    k_mv1<<<(DIM * 32 + 255) / 256, 256>>>(W1, b1);
    k_mv2<<<(DIM * 32 + 255) / 256, 256>>>(W2, b2, out);
}